// round 4
// baseline (speedup 1.0000x reference)
#include <cuda_runtime.h>
#include <math.h>
#include <float.h>

#define NLAT 64
#define NLON 128
#define GPTS 8192   // NLAT*NLON
#define NS   1024   // stations
#define HD   256    // hidden dim
#define NB   2      // batch

// Normalized softmax weights, layout [b][s][g] (g contiguous).
__device__ float g_P[(size_t)NB * NS * GPTS];

// ---------------------------------------------------------------------------
// packed fp32x2 helpers (sm_100+ PTX; ptxas never auto-emits FFMA2)
// ---------------------------------------------------------------------------
typedef unsigned long long u64p;

__device__ __forceinline__ u64p pk2(float lo, float hi)
{ u64p r; asm("mov.b64 %0, {%1, %2};" : "=l"(r) : "f"(lo), "f"(hi)); return r; }

__device__ __forceinline__ void up2(u64p v, float& lo, float& hi)
{ asm("mov.b64 {%0, %1}, %2;" : "=f"(lo), "=f"(hi) : "l"(v)); }

__device__ __forceinline__ u64p fma2(u64p a, u64p b, u64p c)
{ u64p d; asm("fma.rn.f32x2 %0, %1, %2, %3;" : "=l"(d) : "l"(a), "l"(b), "l"(c)); return d; }

__device__ __forceinline__ u64p mul2(u64p a, u64p b)
{ u64p d; asm("mul.rn.f32x2 %0, %1, %2;" : "=l"(d) : "l"(a), "l"(b)); return d; }

__device__ __forceinline__ u64p add2(u64p a, u64p b)
{ u64p d; asm("add.rn.f32x2 %0, %1, %2;" : "=l"(d) : "l"(a), "l"(b)); return d; }

__device__ __forceinline__ float tanhap(float x)
{ float t; asm("tanh.approx.f32 %0, %1;" : "=f"(t) : "f"(x)); return t; }

// ---------------------------------------------------------------------------
// Phase 1: logits + fused online softmax, two stations packed per f32x2.
// Grid (GPTS/32, NB), 256 threads = 8 warps.
// lane -> g = blockIdx.x*32 + lane; warp -> 128-station chunk.
// ---------------------------------------------------------------------------
__global__ __launch_bounds__(256) void weights_kernel(
    const float* __restrict__ coords,   // [B, S, 3]
    const float* __restrict__ mask,     // [B, S]
    const float* __restrict__ W1,       // [3, 32]
    const float* __restrict__ b1,       // [32]
    const float* __restrict__ W2,       // [32, 1]
    const float* __restrict__ b2)       // [1]
{
    // weights stored DUPLICATED: sW0d[2j] == sW0d[2j+1] == W1[0][j], so one
    // LDS.128 yields dup-packed pairs for two hidden units.
    __shared__ __align__(16) float sW0d[64];
    __shared__ __align__(16) float sWad[64];
    __shared__ __align__(16) float sWod[64];
    __shared__ __align__(16) float sB1d[64];
    __shared__ __align__(16) float sW2d[64];
    __shared__ float sLat[NS];
    __shared__ float sLon[NS];
    __shared__ float sMask[NS];
    __shared__ float sb2s;
    __shared__ float red_m[8][32];
    __shared__ float red_s[8][32];

    const int tid  = threadIdx.x;
    const int lane = tid & 31;
    const int wrp  = tid >> 5;
    const int b    = blockIdx.y;

    if (tid < 64) {
        const int j = tid >> 1;
        sW0d[tid] = W1[j];
        sWad[tid] = W1[32 + j];
        sWod[tid] = W1[64 + j];
        sB1d[tid] = b1[j];
        sW2d[tid] = W2[j];
    }
    if (tid == 0) sb2s = b2[0];

    for (int s = tid; s < NS; s += 256) {
        sLat[s]  = coords[((size_t)b * NS + s) * 3 + 0];
        sLon[s]  = coords[((size_t)b * NS + s) * 3 + 1];
        sMask[s] = mask[(size_t)b * NS + s];
    }
    __syncthreads();

    const int g = blockIdx.x * 32 + lane;
    const float glat = -90.0f  + (float)(g >> 7)  * (180.0f / 63.0f);
    const float glon = -180.0f + (float)(g & 127) * (360.0f / 127.0f);

    const u64p nglat2 = pk2(-glat, -glat);
    const u64p nglon2 = pk2(-glon, -glon);
    const u64p EPS2   = pk2(1e-6f, 1e-6f);
    const u64p C0_2   = pk2(0.7978845608f, 0.7978845608f);
    const u64p C1_2   = pk2(0.0356774081f, 0.0356774081f);
    const u64p H2     = pk2(0.5f, 0.5f);
    const u64p B2V    = pk2(sb2s, sb2s);

    float* Pb = g_P + (size_t)b * NS * GPTS;

    float m_run = -FLT_MAX;
    float s_run = 0.0f;
    const int s_base = wrp * 128;

#pragma unroll 1
    for (int it = 0; it < 128; it += 2) {
        const int s0 = s_base + it;
        const int s1 = s0 + 1;

        const u64p slatp = pk2(sLat[s0], sLat[s1]);
        const u64p slonp = pk2(sLon[s0], sLon[s1]);
        const u64p dlat  = add2(slatp, nglat2);
        const u64p dlon  = add2(slonp, nglon2);
        const u64p dsq   = fma2(dlat, dlat, fma2(dlon, dlon, EPS2));
        float q0, q1; up2(dsq, q0, q1);
        const u64p dist  = pk2(sqrtf(q0), sqrtf(q1));

        u64p acc = B2V;

#pragma unroll
        for (int u2 = 0; u2 < 32; u2 += 2) {
            const ulonglong2 w0 = *(const ulonglong2*)&sW0d[2 * u2];
            const ulonglong2 wa = *(const ulonglong2*)&sWad[2 * u2];
            const ulonglong2 wo = *(const ulonglong2*)&sWod[2 * u2];
            const ulonglong2 bb = *(const ulonglong2*)&sB1d[2 * u2];
            const ulonglong2 w2 = *(const ulonglong2*)&sW2d[2 * u2];

            // unit u2
            u64p z   = fma2(dist, w0.x, fma2(dlat, wa.x, fma2(dlon, wo.x, bb.x)));
            u64p zsq = mul2(z, z);
            u64p uu  = mul2(z, fma2(zsq, C1_2, C0_2));
            float ua, ub; up2(uu, ua, ub);
            u64p tt  = pk2(tanhap(ua), tanhap(ub));
            acc = fma2(mul2(z, fma2(tt, H2, H2)), w2.x, acc);

            // unit u2+1
            z   = fma2(dist, w0.y, fma2(dlat, wa.y, fma2(dlon, wo.y, bb.y)));
            zsq = mul2(z, z);
            uu  = mul2(z, fma2(zsq, C1_2, C0_2));
            up2(uu, ua, ub);
            tt  = pk2(tanhap(ua), tanhap(ub));
            acc = fma2(mul2(z, fma2(tt, H2, H2)), w2.y, acc);
        }

        float a0f, a1f; up2(acc, a0f, a1f);

        // softplus * mask
        const float sp0 = fmaxf(a0f, 0.0f) + __logf(1.0f + __expf(-fabsf(a0f)));
        const float sp1 = fmaxf(a1f, 0.0f) + __logf(1.0f + __expf(-fabsf(a1f)));
        const float l0  = sp0 * sMask[s0];
        const float l1  = sp1 * sMask[s1];

        // online softmax accumulation
        const float mnew = fmaxf(m_run, fmaxf(l0, l1));
        s_run = fmaf(s_run, __expf(m_run - mnew),
                     __expf(l0 - mnew) + __expf(l1 - mnew));
        m_run = mnew;

        Pb[(size_t)s0 * GPTS + g] = l0;
        Pb[(size_t)s1 * GPTS + g] = l1;
    }

    // cross-warp combine (per lane == per g)
    red_m[wrp][lane] = m_run;
    red_s[wrp][lane] = s_run;
    __syncthreads();

    float M = -FLT_MAX;
#pragma unroll
    for (int w = 0; w < 8; w++) M = fmaxf(M, red_m[w][lane]);
    float Stot = 0.0f;
#pragma unroll
    for (int w = 0; w < 8; w++) Stot += red_s[w][lane] * __expf(red_m[w][lane] - M);

    const float inv = 1.0f / Stot;

    // normalize in place
#pragma unroll 1
    for (int it = 0; it < 128; it++) {
        const int s = s_base + it;
        const float l = Pb[(size_t)s * GPTS + g];
        Pb[(size_t)s * GPTS + g] = __expf(l - M) * inv;
    }
}

// ---------------------------------------------------------------------------
// Phase 2: C[g,d] = sum_s P[s,g] * F[s,d]; write out[b,d,g].
// 128x128 tile, BSK=16, double-buffered, 256 threads.
// 8x8 microtile computed as 4 g-pairs x 8 d via FFMA2.
// ---------------------------------------------------------------------------
#define BSK 16

__global__ __launch_bounds__(256, 2) void grid_gemm_kernel(
    const float* __restrict__ F,   // [B, S, D]
    float* __restrict__ out)       // [B, D, G]
{
    __shared__ float As[2][BSK][128];   // [s][g]
    __shared__ float Bs[2][BSK][128];   // [s][d]

    const int tid = threadIdx.x;
    const int tx  = tid & 15;
    const int ty  = tid >> 4;
    const int g0  = blockIdx.x * 128;
    const int d0  = blockIdx.y * 128;
    const int b   = blockIdx.z;

    const float* P  = g_P + (size_t)b * NS * GPTS;
    const float* Fb = F   + (size_t)b * NS * HD;

    // loader indexing: 512 float4 slots per tile, 2 per thread
    const int sl0 = tid >> 5,          v0 = (tid & 31) * 4;
    const int sl1 = (tid + 256) >> 5,  v1 = v0;

    float4 ra0, ra1, rb0, rb1;

    // preload chunk 0
    ra0 = *(const float4*)(P  + (size_t)sl0 * GPTS + g0 + v0);
    ra1 = *(const float4*)(P  + (size_t)sl1 * GPTS + g0 + v1);
    rb0 = *(const float4*)(Fb + (size_t)sl0 * HD   + d0 + v0);
    rb1 = *(const float4*)(Fb + (size_t)sl1 * HD   + d0 + v1);
    *(float4*)&As[0][sl0][v0] = ra0;
    *(float4*)&As[0][sl1][v1] = ra1;
    *(float4*)&Bs[0][sl0][v0] = rb0;
    *(float4*)&Bs[0][sl1][v1] = rb1;
    __syncthreads();

    u64p acc[4][8];
#pragma unroll
    for (int i = 0; i < 4; i++)
#pragma unroll
        for (int j = 0; j < 8; j++) acc[i][j] = 0ull;

    const int NC = NS / BSK;   // 64
#pragma unroll 1
    for (int c = 0; c < NC; c++) {
        const int cur = c & 1;

        if (c + 1 < NC) {
            const int sc = (c + 1) * BSK;
            ra0 = *(const float4*)(P  + (size_t)(sc + sl0) * GPTS + g0 + v0);
            ra1 = *(const float4*)(P  + (size_t)(sc + sl1) * GPTS + g0 + v1);
            rb0 = *(const float4*)(Fb + (size_t)(sc + sl0) * HD   + d0 + v0);
            rb1 = *(const float4*)(Fb + (size_t)(sc + sl1) * HD   + d0 + v1);
        }

#pragma unroll
        for (int ss = 0; ss < BSK; ss++) {
            // A fragments: float4 = 2 packed g-pairs each
            const ulonglong2 a0 = *(const ulonglong2*)&As[cur][ss][tx * 4];
            const ulonglong2 a1 = *(const ulonglong2*)&As[cur][ss][64 + tx * 4];
            const u64p ap[4] = { a0.x, a0.y, a1.x, a1.y };

            // B fragments: duplicate-pack scalars (ALU pipe)
            const float4 bq0 = *(const float4*)&Bs[cur][ss][ty * 4];
            const float4 bq1 = *(const float4*)&Bs[cur][ss][64 + ty * 4];
            const u64p bd[8] = {
                pk2(bq0.x, bq0.x), pk2(bq0.y, bq0.y),
                pk2(bq0.z, bq0.z), pk2(bq0.w, bq0.w),
                pk2(bq1.x, bq1.x), pk2(bq1.y, bq1.y),
                pk2(bq1.z, bq1.z), pk2(bq1.w, bq1.w)
            };

#pragma unroll
            for (int i = 0; i < 4; i++)
#pragma unroll
                for (int j = 0; j < 8; j++)
                    acc[i][j] = fma2(ap[i], bd[j], acc[i][j]);
        }

        if (c + 1 < NC) {
            const int nxt = cur ^ 1;
            *(float4*)&As[nxt][sl0][v0] = ra0;
            *(float4*)&As[nxt][sl1][v1] = ra1;
            *(float4*)&Bs[nxt][sl0][v0] = rb0;
            *(float4*)&Bs[nxt][sl1][v1] = rb1;
            __syncthreads();
        }
    }

    // Epilogue: out[b, d, g]
    float* ob = out + (size_t)b * HD * GPTS;
#pragma unroll
    for (int j = 0; j < 8; j++) {
        const int d = d0 + ((j < 4) ? (ty * 4 + j) : (64 + ty * 4 + j - 4));
        float* orow = ob + (size_t)d * GPTS + g0;
        float x0, x1, x2, x3;
        up2(acc[0][j], x0, x1);
        up2(acc[1][j], x2, x3);
        *(float4*)(orow + tx * 4) = make_float4(x0, x1, x2, x3);
        up2(acc[2][j], x0, x1);
        up2(acc[3][j], x2, x3);
        *(float4*)(orow + 64 + tx * 4) = make_float4(x0, x1, x2, x3);
    }
}

// ---------------------------------------------------------------------------
// kernel_launch
// Inputs: station_features, station_coords, mask, W1, b1, W2, b2
// ---------------------------------------------------------------------------
extern "C" void kernel_launch(void* const* d_in, const int* in_sizes, int n_in,
                              void* d_out, int out_size)
{
    const float* features = (const float*)d_in[0];  // [2,1024,256]
    const float* coords   = (const float*)d_in[1];  // [2,1024,3]
    const float* mask     = (const float*)d_in[2];  // [2,1024]
    const float* W1       = (const float*)d_in[3];  // [3,32]
    const float* b1       = (const float*)d_in[4];  // [32]
    const float* W2       = (const float*)d_in[5];  // [32,1]
    const float* b2       = (const float*)d_in[6];  // [1]
    float* out            = (float*)d_out;          // [2,256,64,128]

    dim3 grid1(GPTS / 32, NB);
    weights_kernel<<<grid1, 256>>>(coords, mask, W1, b1, W2, b2);

    dim3 grid2(GPTS / 128, HD / 128, NB);
    grid_gemm_kernel<<<grid2, 256>>>(features, out);
}

// round 6
// speedup vs baseline: 1.4080x; 1.4080x over previous
#include <cuda_runtime.h>
#include <cuda_bf16.h>
#include <math.h>
#include <float.h>

#define NLAT 64
#define NLON 128
#define GPTS 8192   // NLAT*NLON
#define NS   1024   // stations
#define HD   256    // hidden dim
#define NB   2      // batch

// fp32 logits, [b][g][s]
__device__ float g_L[(size_t)NB * GPTS * NS];
// split-bf16 normalized weights, [b][g][s]
__device__ __nv_bfloat16 g_Ph[(size_t)NB * GPTS * NS];
__device__ __nv_bfloat16 g_Pl[(size_t)NB * GPTS * NS];
// split-bf16 transposed features, [b][d][s]
__device__ __nv_bfloat16 g_Fh[(size_t)NB * HD * NS];
__device__ __nv_bfloat16 g_Fl[(size_t)NB * HD * NS];

// ---------------------------------------------------------------------------
// helpers
// ---------------------------------------------------------------------------
__device__ __forceinline__ float tanhap(float x)
{ float t; asm("tanh.approx.f32 %0, %1;" : "=f"(t) : "f"(x)); return t; }

__device__ __forceinline__ float gelu_tanh(float z)
{
    const float z2 = z * z;
    const float u  = z * fmaf(z2, 0.0356774081f, 0.7978845608f);
    return z * fmaf(tanhap(u), 0.5f, 0.5f);
}

__device__ __forceinline__ unsigned smem_u32(const void* p)
{
    unsigned a;
    asm("{ .reg .u64 t; cvta.to.shared.u64 t, %1; cvt.u32.u64 %0, t; }"
        : "=r"(a) : "l"(p));
    return a;
}

__device__ __forceinline__ void split_bf16(float v, unsigned short& h, unsigned short& l)
{
    const __nv_bfloat16 hb = __float2bfloat16(v);
    const float hf = __bfloat162float(hb);
    const __nv_bfloat16 lb = __float2bfloat16(v - hf);
    h = __bfloat16_as_ushort(hb);
    l = __bfloat16_as_ushort(lb);
}

__device__ __forceinline__ unsigned long long pack4(unsigned short a, unsigned short b,
                                                    unsigned short c, unsigned short d)
{
    return (unsigned long long)a | ((unsigned long long)b << 16)
         | ((unsigned long long)c << 32) | ((unsigned long long)d << 48);
}

// ---------------------------------------------------------------------------
// F transpose+split: F[b][s][d] fp32 -> Fh/Fl [b][d][s] bf16.
// grid (NS/64, HD/64, NB), 256 threads, 64x64 smem tile.
// ---------------------------------------------------------------------------
__global__ __launch_bounds__(256) void fsplit_kernel(const float* __restrict__ F)
{
    __shared__ float tile[64][65];
    const int t  = threadIdx.x;
    const int s0 = blockIdx.x * 64;
    const int d0 = blockIdx.y * 64;
    const int b  = blockIdx.z;

#pragma unroll
    for (int q = 0; q < 4; q++) {
        const int idx   = q * 256 + t;        // 1024 float4 slots
        const int s_loc = idx >> 4;
        const int d4    = (idx & 15) * 4;
        const float4 v = *(const float4*)(F + ((size_t)(b * NS + s0 + s_loc)) * HD + d0 + d4);
        tile[s_loc][d4 + 0] = v.x;
        tile[s_loc][d4 + 1] = v.y;
        tile[s_loc][d4 + 2] = v.z;
        tile[s_loc][d4 + 3] = v.w;
    }
    __syncthreads();

#pragma unroll
    for (int q = 0; q < 4; q++) {
        const int idx   = q * 256 + t;
        const int d_loc = idx >> 4;
        const int s4    = (idx & 15) * 4;
        unsigned short h[4], l[4];
#pragma unroll
        for (int e = 0; e < 4; e++)
            split_bf16(tile[s4 + e][d_loc], h[e], l[e]);
        const size_t off = ((size_t)(b * HD + d0 + d_loc)) * NS + s0 + s4;
        *(unsigned long long*)(g_Fh + off) = pack4(h[0], h[1], h[2], h[3]);
        *(unsigned long long*)(g_Fl + off) = pack4(l[0], l[1], l[2], l[3]);
    }
}

// ---------------------------------------------------------------------------
// Phase 1: logits + fused online softmax (R3 compute core), writing
// logits to g_L[b][g][s] via per-warp smem transpose, then a normalize
// pass that emits split-bf16 Ph/Pl[b][g][s].
// Grid (GPTS/32, NB), 256 threads = 8 warps.
// ---------------------------------------------------------------------------
__global__ __launch_bounds__(256) void weights_kernel(
    const float* __restrict__ coords,   // [B, S, 3]
    const float* __restrict__ mask,     // [B, S]
    const float* __restrict__ W1,       // [3, 32]
    const float* __restrict__ b1,       // [32]
    const float* __restrict__ W2,       // [32, 1]
    const float* __restrict__ b2)       // [1]
{
    __shared__ __align__(16) float sW0[32];
    __shared__ __align__(16) float sWa[32];
    __shared__ __align__(16) float sWo[32];
    __shared__ __align__(16) float sB1[32];
    __shared__ __align__(16) float sW2[32];
    __shared__ float sLat[NS];
    __shared__ float sLon[NS];
    __shared__ float sMask[NS];
    __shared__ float sb2s;
    __shared__ float red_m[8][32];
    __shared__ float red_s[8][32];
    __shared__ float sT[8][32][33];
    __shared__ float sMax[32];
    __shared__ float sInv[32];

    const int tid  = threadIdx.x;
    const int lane = tid & 31;
    const int wrp  = tid >> 5;
    const int b    = blockIdx.y;
    const int g0   = blockIdx.x * 32;
    const size_t bG = (size_t)b * GPTS;

    if (tid < 32) {
        sW0[tid] = W1[tid];
        sWa[tid] = W1[32 + tid];
        sWo[tid] = W1[64 + tid];
        sB1[tid] = b1[tid];
        sW2[tid] = W2[tid];
    }
    if (tid == 0) sb2s = b2[0];

    for (int s = tid; s < NS; s += 256) {
        sLat[s]  = coords[((size_t)b * NS + s) * 3 + 0];
        sLon[s]  = coords[((size_t)b * NS + s) * 3 + 1];
        sMask[s] = mask[(size_t)b * NS + s];
    }
    __syncthreads();

    const int g = g0 + lane;
    const float glat = -90.0f  + (float)(g >> 7)  * (180.0f / 63.0f);
    const float glon = -180.0f + (float)(g & 127) * (360.0f / 127.0f);

    const float b2v = sb2s;

    float m_run = -FLT_MAX;
    float s_run = 0.0f;
    const int s_base = wrp * 128;

#pragma unroll 1
    for (int it = 0; it < 128; it += 2) {
        const int s0 = s_base + it;
        const int s1 = s0 + 1;

        const float dlat0 = sLat[s0] - glat;
        const float dlon0 = sLon[s0] - glon;
        const float dist0 = sqrtf(fmaf(dlat0, dlat0, fmaf(dlon0, dlon0, 1e-6f)));
        const float dlat1 = sLat[s1] - glat;
        const float dlon1 = sLon[s1] - glon;
        const float dist1 = sqrtf(fmaf(dlat1, dlat1, fmaf(dlon1, dlon1, 1e-6f)));

        float acc0 = b2v;
        float acc1 = b2v;

#pragma unroll
        for (int q = 0; q < 8; q++) {
            const float4 w0 = *(const float4*)&sW0[4 * q];
            const float4 wa = *(const float4*)&sWa[4 * q];
            const float4 wo = *(const float4*)&sWo[4 * q];
            const float4 bb = *(const float4*)&sB1[4 * q];
            const float4 w2 = *(const float4*)&sW2[4 * q];

            float z;
            z = fmaf(dist0, w0.x, fmaf(dlat0, wa.x, fmaf(dlon0, wo.x, bb.x)));
            acc0 = fmaf(gelu_tanh(z), w2.x, acc0);
            z = fmaf(dist0, w0.y, fmaf(dlat0, wa.y, fmaf(dlon0, wo.y, bb.y)));
            acc0 = fmaf(gelu_tanh(z), w2.y, acc0);
            z = fmaf(dist0, w0.z, fmaf(dlat0, wa.z, fmaf(dlon0, wo.z, bb.z)));
            acc0 = fmaf(gelu_tanh(z), w2.z, acc0);
            z = fmaf(dist0, w0.w, fmaf(dlat0, wa.w, fmaf(dlon0, wo.w, bb.w)));
            acc0 = fmaf(gelu_tanh(z), w2.w, acc0);

            z = fmaf(dist1, w0.x, fmaf(dlat1, wa.x, fmaf(dlon1, wo.x, bb.x)));
            acc1 = fmaf(gelu_tanh(z), w2.x, acc1);
            z = fmaf(dist1, w0.y, fmaf(dlat1, wa.y, fmaf(dlon1, wo.y, bb.y)));
            acc1 = fmaf(gelu_tanh(z), w2.y, acc1);
            z = fmaf(dist1, w0.z, fmaf(dlat1, wa.z, fmaf(dlon1, wo.z, bb.z)));
            acc1 = fmaf(gelu_tanh(z), w2.z, acc1);
            z = fmaf(dist1, w0.w, fmaf(dlat1, wa.w, fmaf(dlon1, wo.w, bb.w)));
            acc1 = fmaf(gelu_tanh(z), w2.w, acc1);
        }

        const float sp0 = fmaxf(acc0, 0.0f) + __logf(1.0f + __expf(-fabsf(acc0)));
        const float sp1 = fmaxf(acc1, 0.0f) + __logf(1.0f + __expf(-fabsf(acc1)));
        const float l0  = sp0 * sMask[s0];
        const float l1  = sp1 * sMask[s1];

        const float mnew = fmaxf(m_run, fmaxf(l0, l1));
        s_run = fmaf(s_run, __expf(m_run - mnew),
                     __expf(l0 - mnew) + __expf(l1 - mnew));
        m_run = mnew;

        const int c0 = it & 31;
        sT[wrp][lane][c0]     = l0;
        sT[wrp][lane][c0 + 1] = l1;

        if (c0 == 30) {
            __syncwarp();
            const int sblk = s_base + (it & ~31);
#pragma unroll
            for (int r = 0; r < 32; r++)
                g_L[(bG + g0 + r) * NS + sblk + lane] = sT[wrp][r][lane];
            __syncwarp();
        }
    }

    red_m[wrp][lane] = m_run;
    red_s[wrp][lane] = s_run;
    __syncthreads();

    float M = -FLT_MAX;
#pragma unroll
    for (int w = 0; w < 8; w++) M = fmaxf(M, red_m[w][lane]);
    float Stot = 0.0f;
#pragma unroll
    for (int w = 0; w < 8; w++) Stot += red_s[w][lane] * __expf(red_m[w][lane] - M);

    if (wrp == 0) {
        sMax[lane] = M;
        sInv[lane] = 1.0f / Stot;
    }
    __syncthreads();

    // normalize pass: each warp handles 4 g-rows; emit split bf16 [g][s].
#pragma unroll 1
    for (int k = 0; k < 4; k++) {
        const int r  = wrp + 8 * k;
        const float Mr   = sMax[r];
        const float invr = sInv[r];
        const size_t row = (bG + g0 + r) * NS;
#pragma unroll
        for (int cc = 0; cc < 8; cc++) {
            const int s4 = cc * 128 + lane * 4;
            const float4 v = *(const float4*)(g_L + row + s4);
            unsigned short h[4], l[4];
            split_bf16(__expf(v.x - Mr) * invr, h[0], l[0]);
            split_bf16(__expf(v.y - Mr) * invr, h[1], l[1]);
            split_bf16(__expf(v.z - Mr) * invr, h[2], l[2]);
            split_bf16(__expf(v.w - Mr) * invr, h[3], l[3]);
            *(unsigned long long*)(g_Ph + row + s4) = pack4(h[0], h[1], h[2], h[3]);
            *(unsigned long long*)(g_Pl + row + s4) = pack4(l[0], l[1], l[2], l[3]);
        }
    }
}

// ---------------------------------------------------------------------------
// Phase 2: split-bf16 HMMA GEMM via mma.sync.m16n8k16.
// C[d,g] = sum_s Fsp[d,s] * Psp[g,s]  (m=d, n=g, k=s), out[b][d][g].
// Block: 128d x 256g x BK32, 512 threads (16 warps, 2x8), warp tile 64d x 32g.
// Double-buffered cp.async stages; ldmatrix for A; LDS.32 for B.
// ---------------------------------------------------------------------------
#define GBK   32
#define ROWB  80           // padded row stride in bytes (32 bf16 + 8 pad)
#define GA_H  0
#define GA_L  10240        // 128 rows * 80B
#define GB_H  20480
#define GB_L  40960        // + 256 rows * 80B
#define GST   61440        // stage stride
#define GSM_TOTAL (2 * GST)

__device__ __forceinline__ void cpa16(unsigned dst, const void* src)
{
    asm volatile("cp.async.cg.shared.global [%0], [%1], 16;"
                 :: "r"(dst), "l"(__cvta_generic_to_global(src)));
}

__device__ __forceinline__ void ldsm4(unsigned* r, unsigned addr)
{
    asm volatile("ldmatrix.sync.aligned.m8n8.x4.shared.b16 {%0,%1,%2,%3}, [%4];"
                 : "=r"(r[0]), "=r"(r[1]), "=r"(r[2]), "=r"(r[3]) : "r"(addr));
}

__device__ __forceinline__ unsigned lds32(unsigned addr)
{
    unsigned v;
    asm volatile("ld.shared.b32 %0, [%1];" : "=r"(v) : "r"(addr));
    return v;
}

__device__ __forceinline__ void mma16816(float* c, const unsigned* a, unsigned b0, unsigned b1)
{
    asm volatile(
        "mma.sync.aligned.m16n8k16.row.col.f32.bf16.bf16.f32 "
        "{%0,%1,%2,%3}, {%4,%5,%6,%7}, {%8,%9}, {%0,%1,%2,%3};"
        : "+f"(c[0]), "+f"(c[1]), "+f"(c[2]), "+f"(c[3])
        : "r"(a[0]), "r"(a[1]), "r"(a[2]), "r"(a[3]), "r"(b0), "r"(b1));
}

__global__ __launch_bounds__(512, 1) void hmma_gemm_kernel(float* __restrict__ out)
{
    extern __shared__ __align__(16) char smem[];
    const unsigned sb = smem_u32(smem);

    const int t    = threadIdx.x;
    const int wid  = t >> 5;
    const int lane = t & 31;
    const int g0   = blockIdx.x * 256;
    const int d0   = blockIdx.y * 128;
    const int b    = blockIdx.z;

    const int wm = wid & 1;        // d half (64)
    const int wn = wid >> 1;       // g slice of 32
    const int gid = lane >> 2;
    const int tig = lane & 3;

    // fill-thread mapping
    const int a_row  = t >> 2;           // 0..127
    const int a_part = t & 3;

    const __nv_bfloat16* FhB = g_Fh + ((size_t)(b * HD + d0 + a_row)) * NS + a_part * 8;
    const __nv_bfloat16* FlB = g_Fl + ((size_t)(b * HD + d0 + a_row)) * NS + a_part * 8;
    const unsigned a_dst = (unsigned)(a_row * ROWB + a_part * 16);

    const int b_row0  = t >> 1;          // 0..255
    const int b_part0 = (t & 1) * 2;     // parts {0,1} or {2,3}
    const __nv_bfloat16* PhB = g_Ph + ((size_t)b * GPTS + g0 + b_row0) * NS + b_part0 * 8;
    const __nv_bfloat16* PlB = g_Pl + ((size_t)b * GPTS + g0 + b_row0) * NS + b_part0 * 8;
    const unsigned b_dst = (unsigned)(b_row0 * ROWB + b_part0 * 16);

    // prologue: fill stage 0 (chunk 0)
    {
        const unsigned s0 = sb;
        cpa16(s0 + GA_H + a_dst, FhB);
        cpa16(s0 + GA_L + a_dst, FlB);
        cpa16(s0 + GB_H + b_dst, PhB);
        cpa16(s0 + GB_H + b_dst + 16, PhB + 8);
        cpa16(s0 + GB_L + b_dst, PlB);
        cpa16(s0 + GB_L + b_dst + 16, PlB + 8);
        asm volatile("cp.async.commit_group;");
    }

    float acc[4][4][4];
#pragma unroll
    for (int i = 0; i < 4; i++)
#pragma unroll
        for (int j = 0; j < 4; j++)
#pragma unroll
            for (int e = 0; e < 4; e++) acc[i][j][e] = 0.0f;

    // ldmatrix lane addressing for A fragments
    const unsigned am_row = (unsigned)((lane & 7) + ((lane >> 3) & 1) * 8); // 0..15
    const unsigned am_kh  = (unsigned)(lane >> 4);                          // 0/1

    const int NC = NS / GBK;   // 32
#pragma unroll 1
    for (int c = 0; c < NC; c++) {
        const unsigned st = sb + (unsigned)((c & 1) * GST);

        if (c + 1 < NC) {
            const unsigned sn = sb + (unsigned)(((c + 1) & 1) * GST);
            const int sc = (c + 1) * GBK;
            cpa16(sn + GA_H + a_dst, FhB + sc);
            cpa16(sn + GA_L + a_dst, FlB + sc);
            cpa16(sn + GB_H + b_dst, PhB + sc);
            cpa16(sn + GB_H + b_dst + 16, PhB + sc + 8);
            cpa16(sn + GB_L + b_dst, PlB + sc);
            cpa16(sn + GB_L + b_dst + 16, PlB + sc + 8);
            asm volatile("cp.async.commit_group;");
            asm volatile("cp.async.wait_group 1;");
        } else {
            asm volatile("cp.async.wait_group 0;");
        }
        __syncthreads();

#pragma unroll
        for (int kk = 0; kk < 2; kk++) {
            const unsigned kb = (unsigned)(kk * 16 + am_kh * 8) * 2;  // byte offset in row

            unsigned ah[4][4], al[4][4];
#pragma unroll
            for (int i = 0; i < 4; i++) {
                const unsigned rowoff = (unsigned)(wm * 64 + i * 16) + am_row;
                ldsm4(ah[i], st + GA_H + rowoff * ROWB + kb);
                ldsm4(al[i], st + GA_L + rowoff * ROWB + kb);
            }

#pragma unroll
            for (int j = 0; j < 4; j++) {
                const unsigned brow = (unsigned)(wn * 32 + j * 8 + gid) * ROWB
                                    + (unsigned)(kk * 16 + tig * 2) * 2;
                const unsigned bh0 = lds32(st + GB_H + brow);
                const unsigned bh1 = lds32(st + GB_H + brow + 16);
                const unsigned bl0 = lds32(st + GB_L + brow);
                const unsigned bl1 = lds32(st + GB_L + brow + 16);
#pragma unroll
                for (int i = 0; i < 4; i++) {
                    mma16816(acc[i][j], ah[i], bh0, bh1);   // Ah*Bh
                    mma16816(acc[i][j], ah[i], bl0, bl1);   // Ah*Bl
                    mma16816(acc[i][j], al[i], bh0, bh1);   // Al*Bh
                }
            }
        }
        __syncthreads();
    }

    // epilogue: D rows = d, cols = g (contiguous pairs) -> out[b][d][g]
    float* ob = out + (size_t)b * HD * GPTS;
#pragma unroll
    for (int i = 0; i < 4; i++) {
        const int d_r = d0 + wm * 64 + i * 16 + gid;
#pragma unroll
        for (int j = 0; j < 4; j++) {
            const int g_c = g0 + wn * 32 + j * 8 + tig * 2;
            *(float2*)(ob + (size_t)d_r * GPTS + g_c) =
                make_float2(acc[i][j][0], acc[i][j][1]);
            *(float2*)(ob + (size_t)(d_r + 8) * GPTS + g_c) =
                make_float2(acc[i][j][2], acc[i][j][3]);
        }
    }
}

// ---------------------------------------------------------------------------
// kernel_launch
// Inputs: station_features, station_coords, mask, W1, b1, W2, b2
// ---------------------------------------------------------------------------
extern "C" void kernel_launch(void* const* d_in, const int* in_sizes, int n_in,
                              void* d_out, int out_size)
{
    const float* features = (const float*)d_in[0];  // [2,1024,256]
    const float* coords   = (const float*)d_in[1];  // [2,1024,3]
    const float* mask     = (const float*)d_in[2];  // [2,1024]
    const float* W1       = (const float*)d_in[3];  // [3,32]
    const float* b1       = (const float*)d_in[4];  // [32]
    const float* W2       = (const float*)d_in[5];  // [32,1]
    const float* b2       = (const float*)d_in[6];  // [1]
    float* out            = (float*)d_out;          // [2,256,64,128]

    static bool attr_set = false;
    if (!attr_set) {
        cudaFuncSetAttribute(hmma_gemm_kernel,
                             cudaFuncAttributeMaxDynamicSharedMemorySize, GSM_TOTAL);
        attr_set = true;
    }

    dim3 gf(NS / 64, HD / 64, NB);
    fsplit_kernel<<<gf, 256>>>(features);

    dim3 g1(GPTS / 32, NB);
    weights_kernel<<<g1, 256>>>(coords, mask, W1, b1, W2, b2);

    dim3 g2(GPTS / 256, HD / 128, NB);
    hmma_gemm_kernel<<<g2, 512, GSM_TOTAL>>>(out);
}

// round 7
// speedup vs baseline: 1.7093x; 1.2140x over previous
#include <cuda_runtime.h>
#include <cuda_bf16.h>
#include <math.h>
#include <float.h>

#define NLAT 64
#define NLON 128
#define GPTS 8192   // NLAT*NLON
#define NS   1024   // stations
#define HD   256    // hidden dim
#define NB   2      // batch

// fp32 logits, [b][g][s]
__device__ float g_L[(size_t)NB * GPTS * NS];
// split-bf16 normalized weights, [b][g][s]
__device__ __nv_bfloat16 g_Ph[(size_t)NB * GPTS * NS];
__device__ __nv_bfloat16 g_Pl[(size_t)NB * GPTS * NS];
// split-bf16 transposed features, [b][d][s]
__device__ __nv_bfloat16 g_Fh[(size_t)NB * HD * NS];
__device__ __nv_bfloat16 g_Fl[(size_t)NB * HD * NS];

// ---------------------------------------------------------------------------
// helpers
// ---------------------------------------------------------------------------
__device__ __forceinline__ float tanhap(float x)
{ float t; asm("tanh.approx.f32 %0, %1;" : "=f"(t) : "f"(x)); return t; }

__device__ __forceinline__ float gelu_tanh(float z)
{
    const float z2 = z * z;
    const float u  = z * fmaf(z2, 0.0356774081f, 0.7978845608f);
    return z * fmaf(tanhap(u), 0.5f, 0.5f);
}

__device__ __forceinline__ unsigned smem_u32(const void* p)
{
    unsigned a;
    asm("{ .reg .u64 t; cvta.to.shared.u64 t, %1; cvt.u32.u64 %0, t; }"
        : "=r"(a) : "l"(p));
    return a;
}

__device__ __forceinline__ void split_bf16(float v, unsigned short& h, unsigned short& l)
{
    const __nv_bfloat16 hb = __float2bfloat16(v);
    const float hf = __bfloat162float(hb);
    const __nv_bfloat16 lb = __float2bfloat16(v - hf);
    h = __bfloat16_as_ushort(hb);
    l = __bfloat16_as_ushort(lb);
}

__device__ __forceinline__ unsigned long long pack4(unsigned short a, unsigned short b,
                                                    unsigned short c, unsigned short d)
{
    return (unsigned long long)a | ((unsigned long long)b << 16)
         | ((unsigned long long)c << 32) | ((unsigned long long)d << 48);
}

// ---------------------------------------------------------------------------
// F transpose+split: F[b][s][d] fp32 -> Fh/Fl [b][d][s] bf16.
// ---------------------------------------------------------------------------
__global__ __launch_bounds__(256) void fsplit_kernel(const float* __restrict__ F)
{
    __shared__ float tile[64][65];
    const int t  = threadIdx.x;
    const int s0 = blockIdx.x * 64;
    const int d0 = blockIdx.y * 64;
    const int b  = blockIdx.z;

#pragma unroll
    for (int q = 0; q < 4; q++) {
        const int idx   = q * 256 + t;
        const int s_loc = idx >> 4;
        const int d4    = (idx & 15) * 4;
        const float4 v = *(const float4*)(F + ((size_t)(b * NS + s0 + s_loc)) * HD + d0 + d4);
        tile[s_loc][d4 + 0] = v.x;
        tile[s_loc][d4 + 1] = v.y;
        tile[s_loc][d4 + 2] = v.z;
        tile[s_loc][d4 + 3] = v.w;
    }
    __syncthreads();

#pragma unroll
    for (int q = 0; q < 4; q++) {
        const int idx   = q * 256 + t;
        const int d_loc = idx >> 4;
        const int s4    = (idx & 15) * 4;
        unsigned short h[4], l[4];
#pragma unroll
        for (int e = 0; e < 4; e++)
            split_bf16(tile[s4 + e][d_loc], h[e], l[e]);
        const size_t off = ((size_t)(b * HD + d0 + d_loc)) * NS + s0 + s4;
        *(unsigned long long*)(g_Fh + off) = pack4(h[0], h[1], h[2], h[3]);
        *(unsigned long long*)(g_Fl + off) = pack4(l[0], l[1], l[2], l[3]);
    }
}

// ---------------------------------------------------------------------------
// Phase 1: logits + fused online softmax.
// A_j = dlat*Wa_j + b1_j is warp-uniform per station (all lanes share glat);
// computed once per station into double-buffered per-warp smem.
// Grid (GPTS/32, NB), 256 threads = 8 warps.
// ---------------------------------------------------------------------------
__global__ __launch_bounds__(256) void weights_kernel(
    const float* __restrict__ coords,   // [B, S, 3]
    const float* __restrict__ mask,     // [B, S]
    const float* __restrict__ W1,       // [3, 32]
    const float* __restrict__ b1,       // [32]
    const float* __restrict__ W2,       // [32, 1]
    const float* __restrict__ b2)       // [1]
{
    __shared__ __align__(16) float sW0[32];
    __shared__ __align__(16) float sWa[32];
    __shared__ __align__(16) float sWo[32];
    __shared__ __align__(16) float sB1[32];
    __shared__ __align__(16) float sW2[32];
    __shared__ __align__(16) float sA[8][2][2][32];  // [warp][buf][station][unit]
    __shared__ float sLat[NS];
    __shared__ float sLon[NS];
    __shared__ float sMask[NS];
    __shared__ float sb2s;
    __shared__ float red_m[8][32];
    __shared__ float red_s[8][32];
    __shared__ float sT[8][32][33];
    __shared__ float sMax[32];
    __shared__ float sInv[32];

    const int tid  = threadIdx.x;
    const int lane = tid & 31;
    const int wrp  = tid >> 5;
    const int b    = blockIdx.y;
    const int g0   = blockIdx.x * 32;
    const size_t bG = (size_t)b * GPTS;

    if (tid < 32) {
        sW0[tid] = W1[tid];
        sWa[tid] = W1[32 + tid];
        sWo[tid] = W1[64 + tid];
        sB1[tid] = b1[tid];
        sW2[tid] = W2[tid];
    }
    if (tid == 0) sb2s = b2[0];

    for (int s = tid; s < NS; s += 256) {
        sLat[s]  = coords[((size_t)b * NS + s) * 3 + 0];
        sLon[s]  = coords[((size_t)b * NS + s) * 3 + 1];
        sMask[s] = mask[(size_t)b * NS + s];
    }
    __syncthreads();

    const int g = g0 + lane;
    const float glat = -90.0f  + (float)(g >> 7)  * (180.0f / 63.0f);  // warp-uniform
    const float glon = -180.0f + (float)(g & 127) * (360.0f / 127.0f);

    const float b2v = sb2s;
    const float wa_l = sWa[lane];
    const float b1_l = sB1[lane];

    float m_run = -FLT_MAX;
    float s_run = 0.0f;
    const int s_base = wrp * 128;

#pragma unroll 1
    for (int it = 0; it < 128; it += 2) {
        const int s0 = s_base + it;
        const int s1 = s0 + 1;
        const int buf = (it >> 1) & 1;

        const float dlat0 = sLat[s0] - glat;   // warp-uniform value
        const float dlon0 = sLon[s0] - glon;
        const float dist0 = sqrtf(fmaf(dlat0, dlat0, fmaf(dlon0, dlon0, 1e-6f)));
        const float dlat1 = sLat[s1] - glat;
        const float dlon1 = sLon[s1] - glon;
        const float dist1 = sqrtf(fmaf(dlat1, dlat1, fmaf(dlon1, dlon1, 1e-6f)));

        // lane j computes A_j for both stations (warp-uniform per unit)
        sA[wrp][buf][0][lane] = fmaf(dlat0, wa_l, b1_l);
        sA[wrp][buf][1][lane] = fmaf(dlat1, wa_l, b1_l);
        __syncwarp();

        float acc0 = b2v;
        float acc1 = b2v;

#pragma unroll
        for (int q = 0; q < 8; q++) {
            const float4 w0 = *(const float4*)&sW0[4 * q];
            const float4 wo = *(const float4*)&sWo[4 * q];
            const float4 w2 = *(const float4*)&sW2[4 * q];
            const float4 a0 = *(const float4*)&sA[wrp][buf][0][4 * q];
            const float4 a1 = *(const float4*)&sA[wrp][buf][1][4 * q];

            float z;
            z = fmaf(dist0, w0.x, fmaf(dlon0, wo.x, a0.x));
            acc0 = fmaf(gelu_tanh(z), w2.x, acc0);
            z = fmaf(dist0, w0.y, fmaf(dlon0, wo.y, a0.y));
            acc0 = fmaf(gelu_tanh(z), w2.y, acc0);
            z = fmaf(dist0, w0.z, fmaf(dlon0, wo.z, a0.z));
            acc0 = fmaf(gelu_tanh(z), w2.z, acc0);
            z = fmaf(dist0, w0.w, fmaf(dlon0, wo.w, a0.w));
            acc0 = fmaf(gelu_tanh(z), w2.w, acc0);

            z = fmaf(dist1, w0.x, fmaf(dlon1, wo.x, a1.x));
            acc1 = fmaf(gelu_tanh(z), w2.x, acc1);
            z = fmaf(dist1, w0.y, fmaf(dlon1, wo.y, a1.y));
            acc1 = fmaf(gelu_tanh(z), w2.y, acc1);
            z = fmaf(dist1, w0.z, fmaf(dlon1, wo.z, a1.z));
            acc1 = fmaf(gelu_tanh(z), w2.z, acc1);
            z = fmaf(dist1, w0.w, fmaf(dlon1, wo.w, a1.w));
            acc1 = fmaf(gelu_tanh(z), w2.w, acc1);
        }

        const float sp0 = fmaxf(acc0, 0.0f) + __logf(1.0f + __expf(-fabsf(acc0)));
        const float sp1 = fmaxf(acc1, 0.0f) + __logf(1.0f + __expf(-fabsf(acc1)));
        const float l0  = sp0 * sMask[s0];
        const float l1  = sp1 * sMask[s1];

        const float mnew = fmaxf(m_run, fmaxf(l0, l1));
        s_run = fmaf(s_run, __expf(m_run - mnew),
                     __expf(l0 - mnew) + __expf(l1 - mnew));
        m_run = mnew;

        const int c0 = it & 31;
        sT[wrp][lane][c0]     = l0;
        sT[wrp][lane][c0 + 1] = l1;

        if (c0 == 30) {
            __syncwarp();
            const int sblk = s_base + (it & ~31);
#pragma unroll
            for (int r = 0; r < 32; r++)
                g_L[(bG + g0 + r) * NS + sblk + lane] = sT[wrp][r][lane];
            __syncwarp();
        }
    }

    red_m[wrp][lane] = m_run;
    red_s[wrp][lane] = s_run;
    __syncthreads();

    float M = -FLT_MAX;
#pragma unroll
    for (int w = 0; w < 8; w++) M = fmaxf(M, red_m[w][lane]);
    float Stot = 0.0f;
#pragma unroll
    for (int w = 0; w < 8; w++) Stot += red_s[w][lane] * __expf(red_m[w][lane] - M);

    if (wrp == 0) {
        sMax[lane] = M;
        sInv[lane] = 1.0f / Stot;
    }
    __syncthreads();

    // normalize pass: each warp handles 4 g-rows; emit split bf16 [g][s].
#pragma unroll 1
    for (int k = 0; k < 4; k++) {
        const int r  = wrp + 8 * k;
        const float Mr   = sMax[r];
        const float invr = sInv[r];
        const size_t row = (bG + g0 + r) * NS;
#pragma unroll
        for (int cc = 0; cc < 8; cc++) {
            const int s4 = cc * 128 + lane * 4;
            const float4 v = *(const float4*)(g_L + row + s4);
            unsigned short h[4], l[4];
            split_bf16(__expf(v.x - Mr) * invr, h[0], l[0]);
            split_bf16(__expf(v.y - Mr) * invr, h[1], l[1]);
            split_bf16(__expf(v.z - Mr) * invr, h[2], l[2]);
            split_bf16(__expf(v.w - Mr) * invr, h[3], l[3]);
            *(unsigned long long*)(g_Ph + row + s4) = pack4(h[0], h[1], h[2], h[3]);
            *(unsigned long long*)(g_Pl + row + s4) = pack4(l[0], l[1], l[2], l[3]);
        }
    }
}

// ---------------------------------------------------------------------------
// Phase 2: split-bf16 HMMA GEMM, 3-stage cp.async pipeline, B via ldmatrix.
// C[d,g] = sum_s Fsp[d,s] * Psp[g,s], out[b][d][g].
// Block: 128d x 256g x BK32, 512 threads (16 warps), warp tile 64d x 32g.
// ---------------------------------------------------------------------------
#define GBK   32
#define ROWB  80
#define GA_H  0
#define GA_L  10240
#define GB_H  20480
#define GB_L  40960
#define GST   61440
#define GSM_TOTAL (3 * GST)

__device__ __forceinline__ void cpa16(unsigned dst, const void* src)
{
    asm volatile("cp.async.cg.shared.global [%0], [%1], 16;"
                 :: "r"(dst), "l"(__cvta_generic_to_global(src)));
}

__device__ __forceinline__ void ldsm4(unsigned* r, unsigned addr)
{
    asm volatile("ldmatrix.sync.aligned.m8n8.x4.shared.b16 {%0,%1,%2,%3}, [%4];"
                 : "=r"(r[0]), "=r"(r[1]), "=r"(r[2]), "=r"(r[3]) : "r"(addr));
}

__device__ __forceinline__ void mma16816(float* c, const unsigned* a, unsigned b0, unsigned b1)
{
    asm volatile(
        "mma.sync.aligned.m16n8k16.row.col.f32.bf16.bf16.f32 "
        "{%0,%1,%2,%3}, {%4,%5,%6,%7}, {%8,%9}, {%0,%1,%2,%3};"
        : "+f"(c[0]), "+f"(c[1]), "+f"(c[2]), "+f"(c[3])
        : "r"(a[0]), "r"(a[1]), "r"(a[2]), "r"(a[3]), "r"(b0), "r"(b1));
}

__global__ __launch_bounds__(512, 1) void hmma_gemm_kernel(float* __restrict__ out)
{
    extern __shared__ __align__(16) char smem[];
    const unsigned sb = smem_u32(smem);

    const int t    = threadIdx.x;
    const int wid  = t >> 5;
    const int lane = t & 31;
    const int g0   = blockIdx.x * 256;
    const int d0   = blockIdx.y * 128;
    const int b    = blockIdx.z;

    const int wm = wid & 1;        // d half (64)
    const int wn = wid >> 1;       // g slice of 32
    const int gid = lane >> 2;
    const int tig = lane & 3;

    // fill-thread mapping
    const int a_row  = t >> 2;
    const int a_part = t & 3;
    const __nv_bfloat16* FhB = g_Fh + ((size_t)(b * HD + d0 + a_row)) * NS + a_part * 8;
    const __nv_bfloat16* FlB = g_Fl + ((size_t)(b * HD + d0 + a_row)) * NS + a_part * 8;
    const unsigned a_dst = (unsigned)(a_row * ROWB + a_part * 16);

    const int b_row0  = t >> 1;
    const int b_part0 = (t & 1) * 2;
    const __nv_bfloat16* PhB = g_Ph + ((size_t)b * GPTS + g0 + b_row0) * NS + b_part0 * 8;
    const __nv_bfloat16* PlB = g_Pl + ((size_t)b * GPTS + g0 + b_row0) * NS + b_part0 * 8;
    const unsigned b_dst = (unsigned)(b_row0 * ROWB + b_part0 * 16);

    const int NC = NS / GBK;   // 32

    // prologue: fill stages 0 and 1 (chunks 0, 1)
#pragma unroll
    for (int p = 0; p < 2; p++) {
        const unsigned sn = sb + (unsigned)(p * GST);
        const int sc = p * GBK;
        cpa16(sn + GA_H + a_dst, FhB + sc);
        cpa16(sn + GA_L + a_dst, FlB + sc);
        cpa16(sn + GB_H + b_dst, PhB + sc);
        cpa16(sn + GB_H + b_dst + 16, PhB + sc + 8);
        cpa16(sn + GB_L + b_dst, PlB + sc);
        cpa16(sn + GB_L + b_dst + 16, PlB + sc + 8);
        asm volatile("cp.async.commit_group;");
    }

    float acc[4][4][4];
#pragma unroll
    for (int i = 0; i < 4; i++)
#pragma unroll
        for (int j = 0; j < 4; j++)
#pragma unroll
            for (int e = 0; e < 4; e++) acc[i][j][e] = 0.0f;

    const unsigned am_row = (unsigned)((lane & 7) + ((lane >> 3) & 1) * 8);
    const unsigned am_kh  = (unsigned)(lane >> 4);
    // B ldmatrix lane addressing
    const unsigned bm_row = (unsigned)(((lane >> 4) & 1) * 8 + (lane & 7));
    const unsigned bm_kb  = (unsigned)(((lane >> 3) & 1) * 16);

    int stage = 0;
#pragma unroll 1
    for (int c = 0; c < NC; c++) {
        const unsigned st = sb + (unsigned)(stage * GST);

        if (c + 2 < NC) {
            int pst = stage + 2; if (pst >= 3) pst -= 3;
            const unsigned sn = sb + (unsigned)(pst * GST);
            const int sc = (c + 2) * GBK;
            cpa16(sn + GA_H + a_dst, FhB + sc);
            cpa16(sn + GA_L + a_dst, FlB + sc);
            cpa16(sn + GB_H + b_dst, PhB + sc);
            cpa16(sn + GB_H + b_dst + 16, PhB + sc + 8);
            cpa16(sn + GB_L + b_dst, PlB + sc);
            cpa16(sn + GB_L + b_dst + 16, PlB + sc + 8);
            asm volatile("cp.async.commit_group;");
            asm volatile("cp.async.wait_group 2;");
        } else if (c + 1 < NC) {
            asm volatile("cp.async.wait_group 1;");
        } else {
            asm volatile("cp.async.wait_group 0;");
        }
        __syncthreads();

#pragma unroll
        for (int kk = 0; kk < 2; kk++) {
            const unsigned kb = (unsigned)(kk * 16 + am_kh * 8) * 2;

            unsigned ah[4][4], al[4][4];
#pragma unroll
            for (int i = 0; i < 4; i++) {
                const unsigned rowoff = (unsigned)(wm * 64 + i * 16) + am_row;
                ldsm4(ah[i], st + GA_H + rowoff * ROWB + kb);
                ldsm4(al[i], st + GA_L + rowoff * ROWB + kb);
            }

#pragma unroll
            for (int jp = 0; jp < 2; jp++) {
                const unsigned brow = (unsigned)(wn * 32 + jp * 16) + bm_row;
                const unsigned bcol = (unsigned)(kk * 32) + bm_kb;
                unsigned bh[4], bl[4];
                ldsm4(bh, st + GB_H + brow * ROWB + bcol);
                ldsm4(bl, st + GB_L + brow * ROWB + bcol);
#pragma unroll
                for (int jj = 0; jj < 2; jj++) {
                    const int j = jp * 2 + jj;
#pragma unroll
                    for (int i = 0; i < 4; i++) {
                        mma16816(acc[i][j], ah[i], bh[2*jj], bh[2*jj+1]);
                        mma16816(acc[i][j], ah[i], bl[2*jj], bl[2*jj+1]);
                        mma16816(acc[i][j], al[i], bh[2*jj], bh[2*jj+1]);
                    }
                }
            }
        }
        __syncthreads();

        if (++stage >= 3) stage = 0;
    }

    // epilogue: out[b][d][g]
    float* ob = out + (size_t)b * HD * GPTS;
#pragma unroll
    for (int i = 0; i < 4; i++) {
        const int d_r = d0 + wm * 64 + i * 16 + gid;
#pragma unroll
        for (int j = 0; j < 4; j++) {
            const int g_c = g0 + wn * 32 + j * 8 + tig * 2;
            *(float2*)(ob + (size_t)d_r * GPTS + g_c) =
                make_float2(acc[i][j][0], acc[i][j][1]);
            *(float2*)(ob + (size_t)(d_r + 8) * GPTS + g_c) =
                make_float2(acc[i][j][2], acc[i][j][3]);
        }
    }
}

// ---------------------------------------------------------------------------
// kernel_launch
// Inputs: station_features, station_coords, mask, W1, b1, W2, b2
// ---------------------------------------------------------------------------
extern "C" void kernel_launch(void* const* d_in, const int* in_sizes, int n_in,
                              void* d_out, int out_size)
{
    const float* features = (const float*)d_in[0];  // [2,1024,256]
    const float* coords   = (const float*)d_in[1];  // [2,1024,3]
    const float* mask     = (const float*)d_in[2];  // [2,1024]
    const float* W1       = (const float*)d_in[3];  // [3,32]
    const float* b1       = (const float*)d_in[4];  // [32]
    const float* W2       = (const float*)d_in[5];  // [32,1]
    const float* b2       = (const float*)d_in[6];  // [1]
    float* out            = (float*)d_out;          // [2,256,64,128]

    static bool attr_set = false;
    if (!attr_set) {
        cudaFuncSetAttribute(hmma_gemm_kernel,
                             cudaFuncAttributeMaxDynamicSharedMemorySize, GSM_TOTAL);
        attr_set = true;
    }

    dim3 gf(NS / 64, HD / 64, NB);
    fsplit_kernel<<<gf, 256>>>(features);

    dim3 g1(GPTS / 32, NB);
    weights_kernel<<<g1, 256>>>(coords, mask, W1, b1, W2, b2);

    dim3 g2(GPTS / 256, HD / 128, NB);
    hmma_gemm_kernel<<<g2, 512, GSM_TOTAL>>>(out);
}

// round 8
// speedup vs baseline: 1.8454x; 1.0796x over previous
#include <cuda_runtime.h>
#include <cuda_bf16.h>
#include <math.h>
#include <float.h>

#define NLAT 64
#define NLON 128
#define GPTS 8192   // NLAT*NLON
#define NS   1024   // stations
#define HD   256    // hidden dim
#define NB   2      // batch

// fp32 logits, [b][g][s]
__device__ float g_L[(size_t)NB * GPTS * NS];
// split-bf16 normalized weights, [b][g][s]
__device__ __nv_bfloat16 g_Ph[(size_t)NB * GPTS * NS];
__device__ __nv_bfloat16 g_Pl[(size_t)NB * GPTS * NS];
// split-bf16 transposed features, [b][d][s]
__device__ __nv_bfloat16 g_Fh[(size_t)NB * HD * NS];
__device__ __nv_bfloat16 g_Fl[(size_t)NB * HD * NS];

// ---------------------------------------------------------------------------
// helpers
// ---------------------------------------------------------------------------
__device__ __forceinline__ float tanhap(float x)
{ float t; asm("tanh.approx.f32 %0, %1;" : "=f"(t) : "f"(x)); return t; }

__device__ __forceinline__ float sqrtap(float x)
{ float r; asm("sqrt.approx.f32 %0, %1;" : "=f"(r) : "f"(x)); return r; }

__device__ __forceinline__ unsigned smem_u32(const void* p)
{
    unsigned a;
    asm("{ .reg .u64 t; cvta.to.shared.u64 t, %1; cvt.u32.u64 %0, t; }"
        : "=r"(a) : "l"(p));
    return a;
}

__device__ __forceinline__ void split_bf16(float v, unsigned short& h, unsigned short& l)
{
    const __nv_bfloat16 hb = __float2bfloat16(v);
    const float hf = __bfloat162float(hb);
    const __nv_bfloat16 lb = __float2bfloat16(v - hf);
    h = __bfloat16_as_ushort(hb);
    l = __bfloat16_as_ushort(lb);
}

__device__ __forceinline__ unsigned long long pack4(unsigned short a, unsigned short b,
                                                    unsigned short c, unsigned short d)
{
    return (unsigned long long)a | ((unsigned long long)b << 16)
         | ((unsigned long long)c << 32) | ((unsigned long long)d << 48);
}

// nonlinear GELU contribution: y*tanh(u) with y = z*v
__device__ __forceinline__ void unit_eval(float dist, float dlon,
                                          float w0, float wo, float a, float v,
                                          float& acc)
{
    const float z  = fmaf(dist, w0, fmaf(dlon, wo, a));
    const float y  = z * v;
    const float z2 = z * z;
    const float u  = z * fmaf(z2, 0.0356774081f, 0.7978845608f);
    acc = fmaf(y, tanhap(u), acc);
}

// ---------------------------------------------------------------------------
// F transpose+split: F[b][s][d] fp32 -> Fh/Fl [b][d][s] bf16.
// ---------------------------------------------------------------------------
__global__ __launch_bounds__(256) void fsplit_kernel(const float* __restrict__ F)
{
    __shared__ float tile[64][65];
    const int t  = threadIdx.x;
    const int s0 = blockIdx.x * 64;
    const int d0 = blockIdx.y * 64;
    const int b  = blockIdx.z;

#pragma unroll
    for (int q = 0; q < 4; q++) {
        const int idx   = q * 256 + t;
        const int s_loc = idx >> 4;
        const int d4    = (idx & 15) * 4;
        const float4 v = *(const float4*)(F + ((size_t)(b * NS + s0 + s_loc)) * HD + d0 + d4);
        tile[s_loc][d4 + 0] = v.x;
        tile[s_loc][d4 + 1] = v.y;
        tile[s_loc][d4 + 2] = v.z;
        tile[s_loc][d4 + 3] = v.w;
    }
    __syncthreads();

#pragma unroll
    for (int q = 0; q < 4; q++) {
        const int idx   = q * 256 + t;
        const int d_loc = idx >> 4;
        const int s4    = (idx & 15) * 4;
        unsigned short h[4], l[4];
#pragma unroll
        for (int e = 0; e < 4; e++)
            split_bf16(tile[s4 + e][d_loc], h[e], l[e]);
        const size_t off = ((size_t)(b * HD + d0 + d_loc)) * NS + s0 + s4;
        *(unsigned long long*)(g_Fh + off) = pack4(h[0], h[1], h[2], h[3]);
        *(unsigned long long*)(g_Fl + off) = pack4(l[0], l[1], l[2], l[3]);
    }
}

// ---------------------------------------------------------------------------
// Phase 1: logits + fused online softmax.
// GELU linear part extracted: logit_pre = dist*S0 + dlon*So + dlat*Sa + Sb+b2
//                                        + sum_j (z_j*v_j)*tanh(u_j),  v=W2/2.
// A_j = dlat*Wa_j + b1_j warp-uniform per station (double-buffered smem).
// Grid (GPTS/32, NB), 256 threads = 8 warps.
// ---------------------------------------------------------------------------
__global__ __launch_bounds__(256) void weights_kernel(
    const float* __restrict__ coords,   // [B, S, 3]
    const float* __restrict__ mask,     // [B, S]
    const float* __restrict__ W1,       // [3, 32]
    const float* __restrict__ b1,       // [32]
    const float* __restrict__ W2,       // [32, 1]
    const float* __restrict__ b2)       // [1]
{
    __shared__ __align__(16) float sW0[32];
    __shared__ __align__(16) float sWa[32];
    __shared__ __align__(16) float sWo[32];
    __shared__ __align__(16) float sB1[32];
    __shared__ __align__(16) float sV[32];           // W2/2
    __shared__ __align__(16) float sA[8][2][2][32];  // [warp][buf][station][unit]
    __shared__ float sLat[NS];
    __shared__ float sLon[NS];
    __shared__ float sMask[NS];
    __shared__ float sS0, sSa, sSo, sSbb;            // linear-part dots (Sb + b2)
    __shared__ float red_m[8][32];
    __shared__ float red_s[8][32];
    __shared__ float sT[8][32][33];
    __shared__ float sMax[32];
    __shared__ float sInv[32];

    const int tid  = threadIdx.x;
    const int lane = tid & 31;
    const int wrp  = tid >> 5;
    const int b    = blockIdx.y;
    const int g0   = blockIdx.x * 32;
    const size_t bG = (size_t)b * GPTS;

    if (tid < 32) {
        sW0[tid] = W1[tid];
        sWa[tid] = W1[32 + tid];
        sWo[tid] = W1[64 + tid];
        sB1[tid] = b1[tid];
        sV[tid]  = 0.5f * W2[tid];
    }

    for (int s = tid; s < NS; s += 256) {
        sLat[s]  = coords[((size_t)b * NS + s) * 3 + 0];
        sLon[s]  = coords[((size_t)b * NS + s) * 3 + 1];
        sMask[s] = mask[(size_t)b * NS + s];
    }
    __syncthreads();

    if (wrp == 0) {
        const float v = sV[lane];
        float p0 = sW0[lane] * v;
        float pa = sWa[lane] * v;
        float po = sWo[lane] * v;
        float pb = sB1[lane] * v;
#pragma unroll
        for (int off = 16; off > 0; off >>= 1) {
            p0 += __shfl_xor_sync(0xffffffffu, p0, off);
            pa += __shfl_xor_sync(0xffffffffu, pa, off);
            po += __shfl_xor_sync(0xffffffffu, po, off);
            pb += __shfl_xor_sync(0xffffffffu, pb, off);
        }
        if (lane == 0) {
            sS0 = p0; sSa = pa; sSo = po; sSbb = pb + b2[0];
        }
    }
    __syncthreads();

    const int g = g0 + lane;
    const float glat = -90.0f  + (float)(g >> 7)  * (180.0f / 63.0f);  // warp-uniform
    const float glon = -180.0f + (float)(g & 127) * (360.0f / 127.0f);

    const float S0v = sS0, Sav = sSa, Sov = sSo, Sbb = sSbb;
    const float wa_l = sWa[lane];
    const float b1_l = sB1[lane];

    float m_run = -FLT_MAX;
    float s_run = 0.0f;
    const int s_base = wrp * 128;

#pragma unroll 1
    for (int it = 0; it < 128; it += 2) {
        const int s0 = s_base + it;
        const int s1 = s0 + 1;
        const int buf = (it >> 1) & 1;

        const float dlat0 = sLat[s0] - glat;
        const float dlon0 = sLon[s0] - glon;
        const float dist0 = sqrtap(fmaf(dlat0, dlat0, fmaf(dlon0, dlon0, 1e-6f)));
        const float dlat1 = sLat[s1] - glat;
        const float dlon1 = sLon[s1] - glon;
        const float dist1 = sqrtap(fmaf(dlat1, dlat1, fmaf(dlon1, dlon1, 1e-6f)));

        // lane j computes A_j for both stations (warp-uniform per unit)
        sA[wrp][buf][0][lane] = fmaf(dlat0, wa_l, b1_l);
        sA[wrp][buf][1][lane] = fmaf(dlat1, wa_l, b1_l);
        __syncwarp();

        // linear part
        float acc0 = 0.0f;
        float acc1 = 0.0f;
        const float lin0 = fmaf(dist0, S0v, fmaf(dlon0, Sov, fmaf(dlat0, Sav, Sbb)));
        const float lin1 = fmaf(dist1, S0v, fmaf(dlon1, Sov, fmaf(dlat1, Sav, Sbb)));

#pragma unroll
        for (int q = 0; q < 8; q++) {
            const float4 w0 = *(const float4*)&sW0[4 * q];
            const float4 wo = *(const float4*)&sWo[4 * q];
            const float4 vv = *(const float4*)&sV[4 * q];
            const float4 a0 = *(const float4*)&sA[wrp][buf][0][4 * q];
            const float4 a1 = *(const float4*)&sA[wrp][buf][1][4 * q];

            unit_eval(dist0, dlon0, w0.x, wo.x, a0.x, vv.x, acc0);
            unit_eval(dist0, dlon0, w0.y, wo.y, a0.y, vv.y, acc0);
            unit_eval(dist0, dlon0, w0.z, wo.z, a0.z, vv.z, acc0);
            unit_eval(dist0, dlon0, w0.w, wo.w, a0.w, vv.w, acc0);

            unit_eval(dist1, dlon1, w0.x, wo.x, a1.x, vv.x, acc1);
            unit_eval(dist1, dlon1, w0.y, wo.y, a1.y, vv.y, acc1);
            unit_eval(dist1, dlon1, w0.z, wo.z, a1.z, vv.z, acc1);
            unit_eval(dist1, dlon1, w0.w, wo.w, a1.w, vv.w, acc1);
        }

        const float pre0 = lin0 + acc0;
        const float pre1 = lin1 + acc1;

        const float sp0 = fmaxf(pre0, 0.0f) + __logf(1.0f + __expf(-fabsf(pre0)));
        const float sp1 = fmaxf(pre1, 0.0f) + __logf(1.0f + __expf(-fabsf(pre1)));
        const float l0  = sp0 * sMask[s0];
        const float l1  = sp1 * sMask[s1];

        const float mnew = fmaxf(m_run, fmaxf(l0, l1));
        s_run = fmaf(s_run, __expf(m_run - mnew),
                     __expf(l0 - mnew) + __expf(l1 - mnew));
        m_run = mnew;

        const int c0 = it & 31;
        sT[wrp][lane][c0]     = l0;
        sT[wrp][lane][c0 + 1] = l1;

        if (c0 == 30) {
            __syncwarp();
            const int sblk = s_base + (it & ~31);
#pragma unroll
            for (int r = 0; r < 32; r++)
                g_L[(bG + g0 + r) * NS + sblk + lane] = sT[wrp][r][lane];
            __syncwarp();
        }
    }

    red_m[wrp][lane] = m_run;
    red_s[wrp][lane] = s_run;
    __syncthreads();

    float M = -FLT_MAX;
#pragma unroll
    for (int w = 0; w < 8; w++) M = fmaxf(M, red_m[w][lane]);
    float Stot = 0.0f;
#pragma unroll
    for (int w = 0; w < 8; w++) Stot += red_s[w][lane] * __expf(red_m[w][lane] - M);

    if (wrp == 0) {
        sMax[lane] = M;
        sInv[lane] = 1.0f / Stot;
    }
    __syncthreads();

    // normalize pass: each warp handles 4 g-rows; emit split bf16 [g][s].
#pragma unroll 1
    for (int k = 0; k < 4; k++) {
        const int r  = wrp + 8 * k;
        const float Mr   = sMax[r];
        const float invr = sInv[r];
        const size_t row = (bG + g0 + r) * NS;
#pragma unroll
        for (int cc = 0; cc < 8; cc++) {
            const int s4 = cc * 128 + lane * 4;
            const float4 v = *(const float4*)(g_L + row + s4);
            unsigned short h[4], l[4];
            split_bf16(__expf(v.x - Mr) * invr, h[0], l[0]);
            split_bf16(__expf(v.y - Mr) * invr, h[1], l[1]);
            split_bf16(__expf(v.z - Mr) * invr, h[2], l[2]);
            split_bf16(__expf(v.w - Mr) * invr, h[3], l[3]);
            *(unsigned long long*)(g_Ph + row + s4) = pack4(h[0], h[1], h[2], h[3]);
            *(unsigned long long*)(g_Pl + row + s4) = pack4(l[0], l[1], l[2], l[3]);
        }
    }
}

// ---------------------------------------------------------------------------
// Phase 2: split-bf16 HMMA GEMM, 3-stage cp.async pipeline, one sync/iter.
// C[d,g] = sum_s Fsp[d,s] * Psp[g,s], out[b][d][g].
// Block: 128d x 256g x BK32, 512 threads (16 warps), warp tile 64d x 32g.
// ---------------------------------------------------------------------------
#define GBK   32
#define ROWB  80
#define GA_H  0
#define GA_L  10240
#define GB_H  20480
#define GB_L  40960
#define GST   61440
#define GSM_TOTAL (3 * GST)

__device__ __forceinline__ void cpa16(unsigned dst, const void* src)
{
    asm volatile("cp.async.cg.shared.global [%0], [%1], 16;"
                 :: "r"(dst), "l"(__cvta_generic_to_global(src)));
}

__device__ __forceinline__ void ldsm4(unsigned* r, unsigned addr)
{
    asm volatile("ldmatrix.sync.aligned.m8n8.x4.shared.b16 {%0,%1,%2,%3}, [%4];"
                 : "=r"(r[0]), "=r"(r[1]), "=r"(r[2]), "=r"(r[3]) : "r"(addr));
}

__device__ __forceinline__ void mma16816(float* c, const unsigned* a, unsigned b0, unsigned b1)
{
    asm volatile(
        "mma.sync.aligned.m16n8k16.row.col.f32.bf16.bf16.f32 "
        "{%0,%1,%2,%3}, {%4,%5,%6,%7}, {%8,%9}, {%0,%1,%2,%3};"
        : "+f"(c[0]), "+f"(c[1]), "+f"(c[2]), "+f"(c[3])
        : "r"(a[0]), "r"(a[1]), "r"(a[2]), "r"(a[3]), "r"(b0), "r"(b1));
}

__global__ __launch_bounds__(512, 1) void hmma_gemm_kernel(float* __restrict__ out)
{
    extern __shared__ __align__(16) char smem[];
    const unsigned sb = smem_u32(smem);

    const int t    = threadIdx.x;
    const int wid  = t >> 5;
    const int lane = t & 31;
    const int g0   = blockIdx.x * 256;
    const int d0   = blockIdx.y * 128;
    const int b    = blockIdx.z;

    const int wm = wid & 1;
    const int wn = wid >> 1;
    const int gid = lane >> 2;
    const int tig = lane & 3;

    const int a_row  = t >> 2;
    const int a_part = t & 3;
    const __nv_bfloat16* FhB = g_Fh + ((size_t)(b * HD + d0 + a_row)) * NS + a_part * 8;
    const __nv_bfloat16* FlB = g_Fl + ((size_t)(b * HD + d0 + a_row)) * NS + a_part * 8;
    const unsigned a_dst = (unsigned)(a_row * ROWB + a_part * 16);

    const int b_row0  = t >> 1;
    const int b_part0 = (t & 1) * 2;
    const __nv_bfloat16* PhB = g_Ph + ((size_t)b * GPTS + g0 + b_row0) * NS + b_part0 * 8;
    const __nv_bfloat16* PlB = g_Pl + ((size_t)b * GPTS + g0 + b_row0) * NS + b_part0 * 8;
    const unsigned b_dst = (unsigned)(b_row0 * ROWB + b_part0 * 16);

    const int NC = NS / GBK;   // 32

#pragma unroll
    for (int p = 0; p < 2; p++) {
        const unsigned sn = sb + (unsigned)(p * GST);
        const int sc = p * GBK;
        cpa16(sn + GA_H + a_dst, FhB + sc);
        cpa16(sn + GA_L + a_dst, FlB + sc);
        cpa16(sn + GB_H + b_dst, PhB + sc);
        cpa16(sn + GB_H + b_dst + 16, PhB + sc + 8);
        cpa16(sn + GB_L + b_dst, PlB + sc);
        cpa16(sn + GB_L + b_dst + 16, PlB + sc + 8);
        asm volatile("cp.async.commit_group;");
    }

    float acc[4][4][4];
#pragma unroll
    for (int i = 0; i < 4; i++)
#pragma unroll
        for (int j = 0; j < 4; j++)
#pragma unroll
            for (int e = 0; e < 4; e++) acc[i][j][e] = 0.0f;

    const unsigned am_row = (unsigned)((lane & 7) + ((lane >> 3) & 1) * 8);
    const unsigned am_kh  = (unsigned)(lane >> 4);
    const unsigned bm_row = (unsigned)(((lane >> 4) & 1) * 8 + (lane & 7));
    const unsigned bm_kb  = (unsigned)(((lane >> 3) & 1) * 16);

    int stage = 0;
#pragma unroll 1
    for (int c = 0; c < NC; c++) {
        const unsigned st = sb + (unsigned)(stage * GST);

        if (c + 1 < NC) asm volatile("cp.async.wait_group 1;");
        else            asm volatile("cp.async.wait_group 0;");
        __syncthreads();

        if (c + 2 < NC) {
            int pst = stage + 2; if (pst >= 3) pst -= 3;
            const unsigned sn = sb + (unsigned)(pst * GST);
            const int sc = (c + 2) * GBK;
            cpa16(sn + GA_H + a_dst, FhB + sc);
            cpa16(sn + GA_L + a_dst, FlB + sc);
            cpa16(sn + GB_H + b_dst, PhB + sc);
            cpa16(sn + GB_H + b_dst + 16, PhB + sc + 8);
            cpa16(sn + GB_L + b_dst, PlB + sc);
            cpa16(sn + GB_L + b_dst + 16, PlB + sc + 8);
            asm volatile("cp.async.commit_group;");
        }

#pragma unroll
        for (int kk = 0; kk < 2; kk++) {
            const unsigned kb = (unsigned)(kk * 16 + am_kh * 8) * 2;

            unsigned ah[4][4], al[4][4];
#pragma unroll
            for (int i = 0; i < 4; i++) {
                const unsigned rowoff = (unsigned)(wm * 64 + i * 16) + am_row;
                ldsm4(ah[i], st + GA_H + rowoff * ROWB + kb);
                ldsm4(al[i], st + GA_L + rowoff * ROWB + kb);
            }

#pragma unroll
            for (int jp = 0; jp < 2; jp++) {
                const unsigned brow = (unsigned)(wn * 32 + jp * 16) + bm_row;
                const unsigned bcol = (unsigned)(kk * 32) + bm_kb;
                unsigned bh[4], bl[4];
                ldsm4(bh, st + GB_H + brow * ROWB + bcol);
                ldsm4(bl, st + GB_L + brow * ROWB + bcol);
#pragma unroll
                for (int jj = 0; jj < 2; jj++) {
                    const int j = jp * 2 + jj;
#pragma unroll
                    for (int i = 0; i < 4; i++) {
                        mma16816(acc[i][j], ah[i], bh[2*jj], bh[2*jj+1]);
                        mma16816(acc[i][j], ah[i], bl[2*jj], bl[2*jj+1]);
                        mma16816(acc[i][j], al[i], bh[2*jj], bh[2*jj+1]);
                    }
                }
            }
        }

        if (++stage >= 3) stage = 0;
    }

    // epilogue: out[b][d][g]
    float* ob = out + (size_t)b * HD * GPTS;
#pragma unroll
    for (int i = 0; i < 4; i++) {
        const int d_r = d0 + wm * 64 + i * 16 + gid;
#pragma unroll
        for (int j = 0; j < 4; j++) {
            const int g_c = g0 + wn * 32 + j * 8 + tig * 2;
            *(float2*)(ob + (size_t)d_r * GPTS + g_c) =
                make_float2(acc[i][j][0], acc[i][j][1]);
            *(float2*)(ob + (size_t)(d_r + 8) * GPTS + g_c) =
                make_float2(acc[i][j][2], acc[i][j][3]);
        }
    }
}

// ---------------------------------------------------------------------------
// kernel_launch
// Inputs: station_features, station_coords, mask, W1, b1, W2, b2
// ---------------------------------------------------------------------------
extern "C" void kernel_launch(void* const* d_in, const int* in_sizes, int n_in,
                              void* d_out, int out_size)
{
    const float* features = (const float*)d_in[0];  // [2,1024,256]
    const float* coords   = (const float*)d_in[1];  // [2,1024,3]
    const float* mask     = (const float*)d_in[2];  // [2,1024]
    const float* W1       = (const float*)d_in[3];  // [3,32]
    const float* b1       = (const float*)d_in[4];  // [32]
    const float* W2       = (const float*)d_in[5];  // [32,1]
    const float* b2       = (const float*)d_in[6];  // [1]
    float* out            = (float*)d_out;          // [2,256,64,128]

    static bool attr_set = false;
    if (!attr_set) {
        cudaFuncSetAttribute(hmma_gemm_kernel,
                             cudaFuncAttributeMaxDynamicSharedMemorySize, GSM_TOTAL);
        attr_set = true;
    }

    dim3 gf(NS / 64, HD / 64, NB);
    fsplit_kernel<<<gf, 256>>>(features);

    dim3 g1(GPTS / 32, NB);
    weights_kernel<<<g1, 256>>>(coords, mask, W1, b1, W2, b2);

    dim3 g2(GPTS / 256, HD / 128, NB);
    hmma_gemm_kernel<<<g2, 512, GSM_TOTAL>>>(out);
}

// round 9
// speedup vs baseline: 1.9697x; 1.0673x over previous
#include <cuda_runtime.h>
#include <cuda_fp16.h>
#include <math.h>
#include <float.h>

#define NLAT 64
#define NLON 128
#define GPTS 8192   // NLAT*NLON
#define NS   1024   // stations
#define HD   256    // hidden dim
#define NB   2      // batch

// fp32 logits, [b][g][s]
__device__ float g_L[(size_t)NB * GPTS * NS];
// split-fp16 normalized weights, [b][g][s]
__device__ __half g_Ph[(size_t)NB * GPTS * NS];
__device__ __half g_Pl[(size_t)NB * GPTS * NS];
// fp16 transposed features (high part only; low part dropped), [b][d][s]
__device__ __half g_Fh[(size_t)NB * HD * NS];

// ---------------------------------------------------------------------------
// helpers
// ---------------------------------------------------------------------------
__device__ __forceinline__ float tanhap(float x)
{ float t; asm("tanh.approx.f32 %0, %1;" : "=f"(t) : "f"(x)); return t; }

__device__ __forceinline__ float sqrtap(float x)
{ float r; asm("sqrt.approx.f32 %0, %1;" : "=f"(r) : "f"(x)); return r; }

__device__ __forceinline__ unsigned smem_u32(const void* p)
{
    unsigned a;
    asm("{ .reg .u64 t; cvta.to.shared.u64 t, %1; cvt.u32.u64 %0, t; }"
        : "=r"(a) : "l"(p));
    return a;
}

__device__ __forceinline__ void split_fp16(float v, unsigned short& h, unsigned short& l)
{
    const __half hb = __float2half_rn(v);
    const float hf = __half2float(hb);
    const __half lb = __float2half_rn(v - hf);
    h = __half_as_ushort(hb);
    l = __half_as_ushort(lb);
}

__device__ __forceinline__ unsigned long long pack4(unsigned short a, unsigned short b,
                                                    unsigned short c, unsigned short d)
{
    return (unsigned long long)a | ((unsigned long long)b << 16)
         | ((unsigned long long)c << 32) | ((unsigned long long)d << 48);
}

// nonlinear GELU contribution: y*tanh(u) with y = z*v
__device__ __forceinline__ void unit_eval(float dist, float dlon,
                                          float w0, float wo, float a, float v,
                                          float& acc)
{
    const float z  = fmaf(dist, w0, fmaf(dlon, wo, a));
    const float y  = z * v;
    const float z2 = z * z;
    const float u  = z * fmaf(z2, 0.0356774081f, 0.7978845608f);
    acc = fmaf(y, tanhap(u), acc);
}

// ---------------------------------------------------------------------------
// F transpose: F[b][s][d] fp32 -> Fh [b][d][s] fp16 (high part only).
// ---------------------------------------------------------------------------
__global__ __launch_bounds__(256) void fsplit_kernel(const float* __restrict__ F)
{
    __shared__ float tile[64][65];
    const int t  = threadIdx.x;
    const int s0 = blockIdx.x * 64;
    const int d0 = blockIdx.y * 64;
    const int b  = blockIdx.z;

#pragma unroll
    for (int q = 0; q < 4; q++) {
        const int idx   = q * 256 + t;
        const int s_loc = idx >> 4;
        const int d4    = (idx & 15) * 4;
        const float4 v = *(const float4*)(F + ((size_t)(b * NS + s0 + s_loc)) * HD + d0 + d4);
        tile[s_loc][d4 + 0] = v.x;
        tile[s_loc][d4 + 1] = v.y;
        tile[s_loc][d4 + 2] = v.z;
        tile[s_loc][d4 + 3] = v.w;
    }
    __syncthreads();

#pragma unroll
    for (int q = 0; q < 4; q++) {
        const int idx   = q * 256 + t;
        const int d_loc = idx >> 4;
        const int s4    = (idx & 15) * 4;
        unsigned short h[4];
#pragma unroll
        for (int e = 0; e < 4; e++)
            h[e] = __half_as_ushort(__float2half_rn(tile[s4 + e][d_loc]));
        const size_t off = ((size_t)(b * HD + d0 + d_loc)) * NS + s0 + s4;
        *(unsigned long long*)(g_Fh + off) = pack4(h[0], h[1], h[2], h[3]);
    }
}

// ---------------------------------------------------------------------------
// Phase 1: logits + fused online softmax.
// GELU linear part extracted; A_j warp-uniform per station.
// Grid (GPTS/32, NB), 256 threads = 8 warps.
// ---------------------------------------------------------------------------
__global__ __launch_bounds__(256) void weights_kernel(
    const float* __restrict__ coords,   // [B, S, 3]
    const float* __restrict__ mask,     // [B, S]
    const float* __restrict__ W1,       // [3, 32]
    const float* __restrict__ b1,       // [32]
    const float* __restrict__ W2,       // [32, 1]
    const float* __restrict__ b2)       // [1]
{
    __shared__ __align__(16) float sW0[32];
    __shared__ __align__(16) float sWa[32];
    __shared__ __align__(16) float sWo[32];
    __shared__ __align__(16) float sB1[32];
    __shared__ __align__(16) float sV[32];           // W2/2
    __shared__ __align__(16) float sA[8][2][2][32];  // [warp][buf][station][unit]
    __shared__ float sLat[NS];
    __shared__ float sLon[NS];
    __shared__ float sMask[NS];
    __shared__ float sS0, sSa, sSo, sSbb;            // linear-part dots (Sb + b2)
    __shared__ float red_m[8][32];
    __shared__ float red_s[8][32];
    __shared__ float sT[8][32][33];
    __shared__ float sMax[32];
    __shared__ float sInv[32];

    const int tid  = threadIdx.x;
    const int lane = tid & 31;
    const int wrp  = tid >> 5;
    const int b    = blockIdx.y;
    const int g0   = blockIdx.x * 32;
    const size_t bG = (size_t)b * GPTS;

    if (tid < 32) {
        sW0[tid] = W1[tid];
        sWa[tid] = W1[32 + tid];
        sWo[tid] = W1[64 + tid];
        sB1[tid] = b1[tid];
        sV[tid]  = 0.5f * W2[tid];
    }

    for (int s = tid; s < NS; s += 256) {
        sLat[s]  = coords[((size_t)b * NS + s) * 3 + 0];
        sLon[s]  = coords[((size_t)b * NS + s) * 3 + 1];
        sMask[s] = mask[(size_t)b * NS + s];
    }
    __syncthreads();

    if (wrp == 0) {
        const float v = sV[lane];
        float p0 = sW0[lane] * v;
        float pa = sWa[lane] * v;
        float po = sWo[lane] * v;
        float pb = sB1[lane] * v;
#pragma unroll
        for (int off = 16; off > 0; off >>= 1) {
            p0 += __shfl_xor_sync(0xffffffffu, p0, off);
            pa += __shfl_xor_sync(0xffffffffu, pa, off);
            po += __shfl_xor_sync(0xffffffffu, po, off);
            pb += __shfl_xor_sync(0xffffffffu, pb, off);
        }
        if (lane == 0) {
            sS0 = p0; sSa = pa; sSo = po; sSbb = pb + b2[0];
        }
    }
    __syncthreads();

    const int g = g0 + lane;
    const float glat = -90.0f  + (float)(g >> 7)  * (180.0f / 63.0f);  // warp-uniform
    const float glon = -180.0f + (float)(g & 127) * (360.0f / 127.0f);

    const float S0v = sS0, Sav = sSa, Sov = sSo, Sbb = sSbb;
    const float wa_l = sWa[lane];
    const float b1_l = sB1[lane];

    float m_run = -FLT_MAX;
    float s_run = 0.0f;
    const int s_base = wrp * 128;

#pragma unroll 1
    for (int it = 0; it < 128; it += 2) {
        const int s0 = s_base + it;
        const int s1 = s0 + 1;
        const int buf = (it >> 1) & 1;

        const float dlat0 = sLat[s0] - glat;
        const float dlon0 = sLon[s0] - glon;
        const float dist0 = sqrtap(fmaf(dlat0, dlat0, fmaf(dlon0, dlon0, 1e-6f)));
        const float dlat1 = sLat[s1] - glat;
        const float dlon1 = sLon[s1] - glon;
        const float dist1 = sqrtap(fmaf(dlat1, dlat1, fmaf(dlon1, dlon1, 1e-6f)));

        // lane j computes A_j for both stations (warp-uniform per unit)
        sA[wrp][buf][0][lane] = fmaf(dlat0, wa_l, b1_l);
        sA[wrp][buf][1][lane] = fmaf(dlat1, wa_l, b1_l);
        __syncwarp();

        float acc0 = 0.0f;
        float acc1 = 0.0f;
        const float lin0 = fmaf(dist0, S0v, fmaf(dlon0, Sov, fmaf(dlat0, Sav, Sbb)));
        const float lin1 = fmaf(dist1, S0v, fmaf(dlon1, Sov, fmaf(dlat1, Sav, Sbb)));

#pragma unroll
        for (int q = 0; q < 8; q++) {
            const float4 w0 = *(const float4*)&sW0[4 * q];
            const float4 wo = *(const float4*)&sWo[4 * q];
            const float4 vv = *(const float4*)&sV[4 * q];
            const float4 a0 = *(const float4*)&sA[wrp][buf][0][4 * q];
            const float4 a1 = *(const float4*)&sA[wrp][buf][1][4 * q];

            unit_eval(dist0, dlon0, w0.x, wo.x, a0.x, vv.x, acc0);
            unit_eval(dist0, dlon0, w0.y, wo.y, a0.y, vv.y, acc0);
            unit_eval(dist0, dlon0, w0.z, wo.z, a0.z, vv.z, acc0);
            unit_eval(dist0, dlon0, w0.w, wo.w, a0.w, vv.w, acc0);

            unit_eval(dist1, dlon1, w0.x, wo.x, a1.x, vv.x, acc1);
            unit_eval(dist1, dlon1, w0.y, wo.y, a1.y, vv.y, acc1);
            unit_eval(dist1, dlon1, w0.z, wo.z, a1.z, vv.z, acc1);
            unit_eval(dist1, dlon1, w0.w, wo.w, a1.w, vv.w, acc1);
        }

        const float pre0 = lin0 + acc0;
        const float pre1 = lin1 + acc1;

        const float sp0 = fmaxf(pre0, 0.0f) + __logf(1.0f + __expf(-fabsf(pre0)));
        const float sp1 = fmaxf(pre1, 0.0f) + __logf(1.0f + __expf(-fabsf(pre1)));
        const float l0  = sp0 * sMask[s0];
        const float l1  = sp1 * sMask[s1];

        const float mnew = fmaxf(m_run, fmaxf(l0, l1));
        s_run = fmaf(s_run, __expf(m_run - mnew),
                     __expf(l0 - mnew) + __expf(l1 - mnew));
        m_run = mnew;

        const int c0 = it & 31;
        sT[wrp][lane][c0]     = l0;
        sT[wrp][lane][c0 + 1] = l1;

        if (c0 == 30) {
            __syncwarp();
            const int sblk = s_base + (it & ~31);
#pragma unroll
            for (int r = 0; r < 32; r++)
                g_L[(bG + g0 + r) * NS + sblk + lane] = sT[wrp][r][lane];
            __syncwarp();
        }
    }

    red_m[wrp][lane] = m_run;
    red_s[wrp][lane] = s_run;
    __syncthreads();

    float M = -FLT_MAX;
#pragma unroll
    for (int w = 0; w < 8; w++) M = fmaxf(M, red_m[w][lane]);
    float Stot = 0.0f;
#pragma unroll
    for (int w = 0; w < 8; w++) Stot += red_s[w][lane] * __expf(red_m[w][lane] - M);

    if (wrp == 0) {
        sMax[lane] = M;
        sInv[lane] = 1.0f / Stot;
    }
    __syncthreads();

    // normalize pass: each warp handles 4 g-rows; emit split fp16 [g][s].
#pragma unroll 1
    for (int k = 0; k < 4; k++) {
        const int r  = wrp + 8 * k;
        const float Mr   = sMax[r];
        const float invr = sInv[r];
        const size_t row = (bG + g0 + r) * NS;
#pragma unroll
        for (int cc = 0; cc < 8; cc++) {
            const int s4 = cc * 128 + lane * 4;
            const float4 v = *(const float4*)(g_L + row + s4);
            unsigned short h[4], l[4];
            split_fp16(__expf(v.x - Mr) * invr, h[0], l[0]);
            split_fp16(__expf(v.y - Mr) * invr, h[1], l[1]);
            split_fp16(__expf(v.z - Mr) * invr, h[2], l[2]);
            split_fp16(__expf(v.w - Mr) * invr, h[3], l[3]);
            *(unsigned long long*)(g_Ph + row + s4) = pack4(h[0], h[1], h[2], h[3]);
            *(unsigned long long*)(g_Pl + row + s4) = pack4(l[0], l[1], l[2], l[3]);
        }
    }
}

// ---------------------------------------------------------------------------
// Phase 2: fp16 2-product HMMA GEMM (Fh*Ph + Fh*Pl), 3-stage cp.async.
// C[d,g] = sum_s F[d,s] * P[g,s], out[b][d][g].
// Block: 128d x 256g x BK32, 512 threads (16 warps), warp tile 64d x 32g.
// ---------------------------------------------------------------------------
#define GBK   32
#define ROWB  80
#define GA_H  0
#define GB_H  10240
#define GB_L  30720
#define GST   51200
#define GSM_TOTAL (3 * GST)

__device__ __forceinline__ void cpa16(unsigned dst, const void* src)
{
    asm volatile("cp.async.cg.shared.global [%0], [%1], 16;"
                 :: "r"(dst), "l"(__cvta_generic_to_global(src)));
}

__device__ __forceinline__ void ldsm4(unsigned* r, unsigned addr)
{
    asm volatile("ldmatrix.sync.aligned.m8n8.x4.shared.b16 {%0,%1,%2,%3}, [%4];"
                 : "=r"(r[0]), "=r"(r[1]), "=r"(r[2]), "=r"(r[3]) : "r"(addr));
}

__device__ __forceinline__ void mma16816(float* c, const unsigned* a, unsigned b0, unsigned b1)
{
    asm volatile(
        "mma.sync.aligned.m16n8k16.row.col.f32.f16.f16.f32 "
        "{%0,%1,%2,%3}, {%4,%5,%6,%7}, {%8,%9}, {%0,%1,%2,%3};"
        : "+f"(c[0]), "+f"(c[1]), "+f"(c[2]), "+f"(c[3])
        : "r"(a[0]), "r"(a[1]), "r"(a[2]), "r"(a[3]), "r"(b0), "r"(b1));
}

__global__ __launch_bounds__(512, 1) void hmma_gemm_kernel(float* __restrict__ out)
{
    extern __shared__ __align__(16) char smem[];
    const unsigned sb = smem_u32(smem);

    const int t    = threadIdx.x;
    const int wid  = t >> 5;
    const int lane = t & 31;
    const int g0   = blockIdx.x * 256;
    const int d0   = blockIdx.y * 128;
    const int b    = blockIdx.z;

    const int wm = wid & 1;
    const int wn = wid >> 1;
    const int gid = lane >> 2;
    const int tig = lane & 3;

    const int a_row  = t >> 2;
    const int a_part = t & 3;
    const __half* FhB = g_Fh + ((size_t)(b * HD + d0 + a_row)) * NS + a_part * 8;
    const unsigned a_dst = (unsigned)(a_row * ROWB + a_part * 16);

    const int b_row0  = t >> 1;
    const int b_part0 = (t & 1) * 2;
    const __half* PhB = g_Ph + ((size_t)b * GPTS + g0 + b_row0) * NS + b_part0 * 8;
    const __half* PlB = g_Pl + ((size_t)b * GPTS + g0 + b_row0) * NS + b_part0 * 8;
    const unsigned b_dst = (unsigned)(b_row0 * ROWB + b_part0 * 16);

    const int NC = NS / GBK;   // 32

#pragma unroll
    for (int p = 0; p < 2; p++) {
        const unsigned sn = sb + (unsigned)(p * GST);
        const int sc = p * GBK;
        cpa16(sn + GA_H + a_dst, FhB + sc);
        cpa16(sn + GB_H + b_dst, PhB + sc);
        cpa16(sn + GB_H + b_dst + 16, PhB + sc + 8);
        cpa16(sn + GB_L + b_dst, PlB + sc);
        cpa16(sn + GB_L + b_dst + 16, PlB + sc + 8);
        asm volatile("cp.async.commit_group;");
    }

    float acc[4][4][4];
#pragma unroll
    for (int i = 0; i < 4; i++)
#pragma unroll
        for (int j = 0; j < 4; j++)
#pragma unroll
            for (int e = 0; e < 4; e++) acc[i][j][e] = 0.0f;

    const unsigned am_row = (unsigned)((lane & 7) + ((lane >> 3) & 1) * 8);
    const unsigned am_kh  = (unsigned)(lane >> 4);
    const unsigned bm_row = (unsigned)(((lane >> 4) & 1) * 8 + (lane & 7));
    const unsigned bm_kb  = (unsigned)(((lane >> 3) & 1) * 16);

    int stage = 0;
#pragma unroll 1
    for (int c = 0; c < NC; c++) {
        const unsigned st = sb + (unsigned)(stage * GST);

        if (c + 1 < NC) asm volatile("cp.async.wait_group 1;");
        else            asm volatile("cp.async.wait_group 0;");
        __syncthreads();

        if (c + 2 < NC) {
            int pst = stage + 2; if (pst >= 3) pst -= 3;
            const unsigned sn = sb + (unsigned)(pst * GST);
            const int sc = (c + 2) * GBK;
            cpa16(sn + GA_H + a_dst, FhB + sc);
            cpa16(sn + GB_H + b_dst, PhB + sc);
            cpa16(sn + GB_H + b_dst + 16, PhB + sc + 8);
            cpa16(sn + GB_L + b_dst, PlB + sc);
            cpa16(sn + GB_L + b_dst + 16, PlB + sc + 8);
            asm volatile("cp.async.commit_group;");
        }

#pragma unroll
        for (int kk = 0; kk < 2; kk++) {
            const unsigned kb = (unsigned)(kk * 16 + am_kh * 8) * 2;

            unsigned ah[4][4];
#pragma unroll
            for (int i = 0; i < 4; i++) {
                const unsigned rowoff = (unsigned)(wm * 64 + i * 16) + am_row;
                ldsm4(ah[i], st + GA_H + rowoff * ROWB + kb);
            }

#pragma unroll
            for (int jp = 0; jp < 2; jp++) {
                const unsigned brow = (unsigned)(wn * 32 + jp * 16) + bm_row;
                const unsigned bcol = (unsigned)(kk * 32) + bm_kb;
                unsigned bh[4], bl[4];
                ldsm4(bh, st + GB_H + brow * ROWB + bcol);
                ldsm4(bl, st + GB_L + brow * ROWB + bcol);
#pragma unroll
                for (int jj = 0; jj < 2; jj++) {
                    const int j = jp * 2 + jj;
#pragma unroll
                    for (int i = 0; i < 4; i++) {
                        mma16816(acc[i][j], ah[i], bh[2*jj], bh[2*jj+1]);
                        mma16816(acc[i][j], ah[i], bl[2*jj], bl[2*jj+1]);
                    }
                }
            }
        }

        if (++stage >= 3) stage = 0;
    }

    // epilogue: out[b][d][g]
    float* ob = out + (size_t)b * HD * GPTS;
#pragma unroll
    for (int i = 0; i < 4; i++) {
        const int d_r = d0 + wm * 64 + i * 16 + gid;
#pragma unroll
        for (int j = 0; j < 4; j++) {
            const int g_c = g0 + wn * 32 + j * 8 + tig * 2;
            *(float2*)(ob + (size_t)d_r * GPTS + g_c) =
                make_float2(acc[i][j][0], acc[i][j][1]);
            *(float2*)(ob + (size_t)(d_r + 8) * GPTS + g_c) =
                make_float2(acc[i][j][2], acc[i][j][3]);
        }
    }
}

// ---------------------------------------------------------------------------
// kernel_launch
// Inputs: station_features, station_coords, mask, W1, b1, W2, b2
// ---------------------------------------------------------------------------
extern "C" void kernel_launch(void* const* d_in, const int* in_sizes, int n_in,
                              void* d_out, int out_size)
{
    const float* features = (const float*)d_in[0];  // [2,1024,256]
    const float* coords   = (const float*)d_in[1];  // [2,1024,3]
    const float* mask     = (const float*)d_in[2];  // [2,1024]
    const float* W1       = (const float*)d_in[3];  // [3,32]
    const float* b1       = (const float*)d_in[4];  // [32]
    const float* W2       = (const float*)d_in[5];  // [32,1]
    const float* b2       = (const float*)d_in[6];  // [1]
    float* out            = (float*)d_out;          // [2,256,64,128]

    static bool attr_set = false;
    if (!attr_set) {
        cudaFuncSetAttribute(hmma_gemm_kernel,
                             cudaFuncAttributeMaxDynamicSharedMemorySize, GSM_TOTAL);
        attr_set = true;
    }

    dim3 gf(NS / 64, HD / 64, NB);
    fsplit_kernel<<<gf, 256>>>(features);

    dim3 g1(GPTS / 32, NB);
    weights_kernel<<<g1, 256>>>(coords, mask, W1, b1, W2, b2);

    dim3 g2(GPTS / 256, HD / 128, NB);
    hmma_gemm_kernel<<<g2, 512, GSM_TOTAL>>>(out);
}